// round 15
// baseline (speedup 1.0000x reference)
#include <cuda_runtime.h>
#include <cuda_bf16.h>
#include <cstdint>

#define BATCH 8
#define NPTS  8192
#define NCTR  2048          // NPTS * 0.25
#define NSAMP 32
#define C0IN  67
#define C2    128
#define R2    0.25f         // radius^2

// ---------------- scratch (device globals; no allocation allowed) ----------------
__device__ float    g_F0[(size_t)BATCH * NPTS * 64];     // 16 MB, layout (b, j, o)
__device__ unsigned g_progress[BATCH * 32];              // padded: 1 line per batch
__device__ unsigned g_f0done[BATCH * 32];                // padded: 1 line per batch

// ---------------- f32x2 packed helpers ----------------
__device__ __forceinline__ unsigned long long pk2(float lo, float hi) {
    unsigned long long r;
    asm("mov.b64 %0, {%1, %2};" : "=l"(r) : "f"(lo), "f"(hi));
    return r;
}
__device__ __forceinline__ unsigned long long pkb(float v) { return pk2(v, v); }
__device__ __forceinline__ void upk2(unsigned long long v, float& lo, float& hi) {
    asm("mov.b64 {%0, %1}, %2;" : "=f"(lo), "=f"(hi) : "l"(v));
}
#define F2FMA(d, a, b, c) asm("fma.rn.f32x2 %0, %1, %2, %3;" : "=l"(d) : "l"(a), "l"(b), "l"(c))
#define F2ADD(d, a, b)    asm("add.rn.f32x2 %0, %1, %2;"     : "=l"(d) : "l"(a), "l"(b))
#define F2MUL(d, a, b)    asm("mul.rn.f32x2 %0, %1, %2;"     : "=l"(d) : "l"(a), "l"(b))

// ---------------- acquire/release helpers ----------------
__device__ __forceinline__ unsigned ld_acq(const unsigned* p) {
    unsigned v;
    asm volatile("ld.acquire.gpu.global.u32 %0, [%1];" : "=r"(v) : "l"(p) : "memory");
    return v;
}
__device__ __forceinline__ void st_rel(unsigned* p, unsigned v) {
    asm volatile("st.release.gpu.global.u32 [%0], %1;" :: "l"(p), "r"(v) : "memory");
}

__device__ __forceinline__ int expand3(int v) {     // 3-bit -> bits 0,3,6
    return (v & 1) | ((v & 2) << 2) | ((v & 4) << 4);
}

// =====================================================================
// reset: clear the inter-block flags (needed per graph replay)
// =====================================================================
__global__ void reset_kernel()
{
    if (threadIdx.x < BATCH * 32) {
        g_progress[threadIdx.x] = 0;
        g_f0done[threadIdx.x]  = 0;
    }
}

// =====================================================================
// mega-kernel: bid 0-7 FPS | bid 8-71 F0 | bid 72+ ballq+MLP workers
// =====================================================================
#define MLPT 512
#define XROW 260
#define SMEM_FLOATS (4096 + 8192 + 64*XROW + 64*XROW + 256 + 64 + 128)
#define GRID_TOTAL (8 + 64 + BATCH * NCTR / 8)

__global__ void __launch_bounds__(MLPT, 1)
mega_kernel(const float* __restrict__ pos,
            const float* __restrict__ features,
            const float* __restrict__ w0, const float* __restrict__ b0,
            const float* __restrict__ w1, const float* __restrict__ b1,
            const float* __restrict__ w2, const float* __restrict__ b2,
            float* __restrict__ new_xyz,
            float* __restrict__ out_feat)
{
    const int bid = blockIdx.x;
    const int tid = threadIdx.x;
    extern __shared__ float sm[];

    // =================================================================
    // ROLE 1: FPS — exact per-HALF-chunk (256 pt) bbox prune, unified
    // reduction, one barrier per step.
    // =================================================================
    if (bid < 8) {
        const int b = bid;
        const int t = tid;
        const int lane = t & 31, w = t >> 5;
        const float* pb = pos + (size_t)b * NPTS * 3;

        float4*   s_pos4 = (float4*)sm;                  // orig-indexed, NEGATED
        unsigned* s_soid = (unsigned*)(sm + 32768);      // sorted pos -> orig idx
        int*      s_hist = (int*)(sm + 40960);           // 512 bins
        int*      s_wsum = (int*)(sm + 41472);           // 16
        float*    s_gbb  = sm + 41488;                   // 6 global bbox
        float4*   s_wbb  = (float4*)(sm + 41504);        // 16 warps x 2 chunks x {min,max}

        __shared__ unsigned s_vhi[2][16], s_vlo[2][16];
        __shared__ float s_red[6][16];

        // ---- pass 1: load points, fill negated table, local bbox ----
        float mnx = 1e30f, mny = 1e30f, mnz = 1e30f;
        float mxx = -1e30f, mxy = -1e30f, mxz = -1e30f;
        for (int k = 0; k < 16; k++) {
            int p = t + (k << 9);
            float px = pb[3 * p], py = pb[3 * p + 1], pz = pb[3 * p + 2];
            s_pos4[p] = make_float4(-px, -py, -pz, 0.0f);
            mnx = fminf(mnx, px); mxx = fmaxf(mxx, px);
            mny = fminf(mny, py); mxy = fmaxf(mxy, py);
            mnz = fminf(mnz, pz); mxz = fmaxf(mxz, pz);
        }
#pragma unroll
        for (int o = 16; o > 0; o >>= 1) {
            mnx = fminf(mnx, __shfl_xor_sync(0xffffffffu, mnx, o));
            mny = fminf(mny, __shfl_xor_sync(0xffffffffu, mny, o));
            mnz = fminf(mnz, __shfl_xor_sync(0xffffffffu, mnz, o));
            mxx = fmaxf(mxx, __shfl_xor_sync(0xffffffffu, mxx, o));
            mxy = fmaxf(mxy, __shfl_xor_sync(0xffffffffu, mxy, o));
            mxz = fmaxf(mxz, __shfl_xor_sync(0xffffffffu, mxz, o));
        }
        if (lane == 0) {
            s_red[0][w] = mnx; s_red[1][w] = mny; s_red[2][w] = mnz;
            s_red[3][w] = mxx; s_red[4][w] = mxy; s_red[5][w] = mxz;
        }
        s_hist[t] = 0;
        __syncthreads();
        if (w == 0 && lane < 6) {
            float v = s_red[lane][0];
            for (int i = 1; i < 16; i++)
                v = (lane < 3) ? fminf(v, s_red[lane][i]) : fmaxf(v, s_red[lane][i]);
            s_gbb[lane] = v;
        }
        __syncthreads();

        // ---- pass 2: morton keys + histogram ----
        const float bnx = s_gbb[0], bny = s_gbb[1], bnz = s_gbb[2];
        const float sx = 7.9999f / fmaxf(s_gbb[3] - bnx, 1e-20f);
        const float sy = 7.9999f / fmaxf(s_gbb[4] - bny, 1e-20f);
        const float sz = 7.9999f / fmaxf(s_gbb[5] - bnz, 1e-20f);
        unsigned key[16];
        for (int k = 0; k < 16; k++) {
            float4 f = s_pos4[t + (k << 9)];
            int qx = min(7, (int)((-f.x - bnx) * sx));
            int qy = min(7, (int)((-f.y - bny) * sy));
            int qz = min(7, (int)((-f.z - bnz) * sz));
            key[k] = (unsigned)(expand3(qx) | (expand3(qy) << 1) | (expand3(qz) << 2));
            atomicAdd(&s_hist[key[k]], 1);
        }
        __syncthreads();

        // ---- exclusive scan of 512 bins ----
        {
            int v = s_hist[t];
            int inc = v;
#pragma unroll
            for (int o = 1; o < 32; o <<= 1) {
                int n = __shfl_up_sync(0xffffffffu, inc, o);
                if (lane >= o) inc += n;
            }
            if (lane == 31) s_wsum[w] = inc;
            __syncthreads();
            if (w == 0) {
                int ws = (lane < 16) ? s_wsum[lane] : 0;
                int wi = ws;
#pragma unroll
                for (int o = 1; o < 16; o <<= 1) {
                    int n = __shfl_up_sync(0xffffffffu, wi, o);
                    if (lane >= o) wi += n;
                }
                if (lane < 16) s_wsum[lane] = wi - ws;
            }
            __syncthreads();
            int excl = inc - v + s_wsum[w];
            __syncthreads();
            s_hist[t] = excl;
            __syncthreads();
        }

        // ---- scatter: sorted position -> orig idx ----
        for (int k = 0; k < 16; k++) {
            int d = atomicAdd(&s_hist[key[k]], 1);
            s_soid[d] = (unsigned)(t + (k << 9));
        }
        __syncthreads();

        // ---- pack registers from sorted order; bbox per 256-pt chunk ----
        unsigned long long xp[8], yp[8], zp[8];
        float dm[16];
#pragma unroll
        for (int r = 0; r < 8; r++) {
            int p0 = (w << 9) + (r << 6) + lane;
            int p1 = p0 + 32;
            float4 a  = s_pos4[s_soid[p0]];
            float4 c4 = s_pos4[s_soid[p1]];
            xp[r] = pk2(-a.x, -c4.x);                // packed POSITIVE coords
            yp[r] = pk2(-a.y, -c4.y);
            zp[r] = pk2(-a.z, -c4.z);
            dm[2 * r] = 1e10f; dm[2 * r + 1] = 1e10f;
        }
#pragma unroll
        for (int c = 0; c < 2; c++) {
            float wnx = 1e30f, wny = 1e30f, wnz = 1e30f;
            float wxx = -1e30f, wxy = -1e30f, wxz = -1e30f;
#pragma unroll
            for (int r = 4 * c; r < 4 * c + 4; r++) {
                float l0, l1;
                // l0/l1 ARE the positive coordinates (fixed: no double negation)
                upk2(xp[r], l0, l1);
                wnx = fminf(wnx, fminf(l0, l1)); wxx = fmaxf(wxx, fmaxf(l0, l1));
                upk2(yp[r], l0, l1);
                wny = fminf(wny, fminf(l0, l1)); wxy = fmaxf(wxy, fmaxf(l0, l1));
                upk2(zp[r], l0, l1);
                wnz = fminf(wnz, fminf(l0, l1)); wxz = fmaxf(wxz, fmaxf(l0, l1));
            }
#pragma unroll
            for (int o = 16; o > 0; o >>= 1) {
                wnx = fminf(wnx, __shfl_xor_sync(0xffffffffu, wnx, o));
                wny = fminf(wny, __shfl_xor_sync(0xffffffffu, wny, o));
                wnz = fminf(wnz, __shfl_xor_sync(0xffffffffu, wnz, o));
                wxx = fmaxf(wxx, __shfl_xor_sync(0xffffffffu, wxx, o));
                wxy = fmaxf(wxy, __shfl_xor_sync(0xffffffffu, wxy, o));
                wxz = fmaxf(wxz, __shfl_xor_sync(0xffffffffu, wxz, o));
            }
            if (lane == 0) {
                s_wbb[4 * w + 2 * c]     = make_float4(wnx, wny, wnz, 0.0f);
                s_wbb[4 * w + 2 * c + 1] = make_float4(wxx, wxy, wxz, 0.0f);
            }
        }
        if (t == 0) {
            float* nz = new_xyz + (size_t)b * NCTR * 3;
            nz[0] = pb[0]; nz[1] = pb[1]; nz[2] = pb[2];
        }
        __syncthreads();

        float4 nc = s_pos4[0];                        // negated current center
        unsigned wmax_cur = __float_as_uint(1e10f);   // warp dm max (upper bound)
        unsigned vlo_cur = 0;                         // 8192 - argmin-idx

        for (int s = 1; s < NCTR; ++s) {
            const int buf = s & 1;
            const float wm = __uint_as_float(wmax_cur) * 1.0001f;

            // ---- per-chunk exact bbox prune (bbox of POSITIVE coords,
            //      nc is NEGATED center -> b.x + nc.x = min_x - cx) ----
            float4 a0 = s_wbb[4 * w + 0], a1 = s_wbb[4 * w + 1];
            float ddx = fmaxf(fmaxf(a0.x + nc.x, -(a1.x + nc.x)), 0.0f);
            float ddy = fmaxf(fmaxf(a0.y + nc.y, -(a1.y + nc.y)), 0.0f);
            float ddz = fmaxf(fmaxf(a0.z + nc.z, -(a1.z + nc.z)), 0.0f);
            float dbb0 = ddx * ddx;
            dbb0 = fmaf(ddy, ddy, dbb0);
            dbb0 = fmaf(ddz, ddz, dbb0);
            float4 c0 = s_wbb[4 * w + 2], c1 = s_wbb[4 * w + 3];
            ddx = fmaxf(fmaxf(c0.x + nc.x, -(c1.x + nc.x)), 0.0f);
            ddy = fmaxf(fmaxf(c0.y + nc.y, -(c1.y + nc.y)), 0.0f);
            ddz = fmaxf(fmaxf(c0.z + nc.z, -(c1.z + nc.z)), 0.0f);
            float dbb1 = ddx * ddx;
            dbb1 = fmaf(ddy, ddy, dbb1);
            dbb1 = fmaf(ddz, ddz, dbb1);
            const bool act0 = !(dbb0 > wm);
            const bool act1 = !(dbb1 > wm);

            if (act0 | act1) {
                const unsigned long long nx  = pkb(nc.x);
                const unsigned long long ny  = pkb(nc.y);
                const unsigned long long nzp = pkb(nc.z);
                if (act0) {
#pragma unroll
                    for (int k = 0; k < 4; k++) {
                        unsigned long long dx, dy, dz, sq;
                        F2ADD(dx, xp[k], nx);
                        F2ADD(dy, yp[k], ny);
                        F2ADD(dz, zp[k], nzp);
                        F2MUL(sq, dx, dx);
                        F2FMA(sq, dy, dy, sq);
                        F2FMA(sq, dz, dz, sq);   // == scalar fmaf chain (exact)
                        float lo, hi; upk2(sq, lo, hi);
                        dm[2 * k]     = fminf(dm[2 * k], lo);
                        dm[2 * k + 1] = fminf(dm[2 * k + 1], hi);
                    }
                }
                if (act1) {
#pragma unroll
                    for (int k = 4; k < 8; k++) {
                        unsigned long long dx, dy, dz, sq;
                        F2ADD(dx, xp[k], nx);
                        F2ADD(dy, yp[k], ny);
                        F2ADD(dz, zp[k], nzp);
                        F2MUL(sq, dx, dx);
                        F2FMA(sq, dy, dy, sq);
                        F2FMA(sq, dz, dz, sq);
                        float lo, hi; upk2(sq, lo, hi);
                        dm[2 * k]     = fminf(dm[2 * k], lo);
                        dm[2 * k + 1] = fminf(dm[2 * k + 1], hi);
                    }
                }

                // ---- pairwise max tree over all 16 dm (pruned chunk's dm
                //      registers remain VALID — that's what prune proves) ----
                float t8[8];
#pragma unroll
                for (int i = 0; i < 8; i++) t8[i] = fmaxf(dm[2 * i], dm[2 * i + 1]);
                float q0 = fmaxf(t8[0], t8[1]), q1 = fmaxf(t8[2], t8[3]);
                float q2 = fmaxf(t8[4], t8[5]), q3 = fmaxf(t8[6], t8[7]);
                float m = fmaxf(fmaxf(q0, q1), fmaxf(q2, q3));

                unsigned mb = __float_as_uint(m);
                unsigned wmax = __reduce_max_sync(0xffffffffu, mb);
                unsigned cand = 0xffffffffu;
                if (mb == wmax) {
                    unsigned mask = 0;
#pragma unroll
                    for (int j = 0; j < 16; j++)
                        if (__float_as_uint(dm[j]) == wmax) mask |= (1u << j);
                    int j0 = __ffs(mask) - 1;
                    cand = s_soid[(w << 9) + ((j0 >> 1) << 6) + ((j0 & 1) << 5) + lane];
                    unsigned mrest = mask & (mask - 1);
                    while (mrest) {                   // rare in-thread exact ties
                        int j2 = __ffs(mrest) - 1; mrest &= mrest - 1;
                        unsigned o2 = s_soid[(w << 9) + ((j2 >> 1) << 6) + ((j2 & 1) << 5) + lane];
                        cand = min(cand, o2);
                    }
                }
                unsigned widx = __reduce_min_sync(0xffffffffu, cand);  // min ORIG idx
                wmax_cur = wmax;
                vlo_cur = 8192u - widx;
            }

            if (lane == 0) {
                s_vhi[buf][w] = wmax_cur;
                s_vlo[buf][w] = vlo_cur;
            }
            __syncthreads();                          // the ONLY barrier per step

            unsigned v   = (lane < 16) ? s_vhi[buf][lane] : 0u;
            unsigned ghi = __reduce_max_sync(0xffffffffu, v);
            unsigned lo2 = (lane < 16 && v == ghi) ? s_vlo[buf][lane] : 0u;
            unsigned glo = __reduce_max_sync(0xffffffffu, lo2);
            unsigned gidx = 8192u - glo;              // winner ORIG index

            nc = s_pos4[gidx];                        // one broadcast LDS.128
            if (t == 0) {
                float* nz = new_xyz + ((size_t)b * NCTR + s) * 3;
                nz[0] = -nc.x; nz[1] = -nc.y; nz[2] = -nc.z;
                if ((s & 7) == 7) st_rel(&g_progress[b * 32], (unsigned)(s + 1));
            }
        }
        return;
    }

    // =================================================================
    // ROLE 2: F0 precompute. 64 blocks: batch = fb>>3, 1024-pt chunk.
    // =================================================================
    if (bid < 72) {
        const int fb = bid - 8;
        const int b = fb >> 3;
        const int j0 = (fb & 7) * 1024;
        float (*w0t)[64] = (float(*)[64])sm;     // [c][o]

        for (int i = tid; i < 64 * 64; i += MLPT) {
            int c = i >> 6, o = i & 63;
            w0t[c][o] = w0[o * C0IN + 3 + c];
        }
        __syncthreads();

#pragma unroll
        for (int rep = 0; rep < 2; rep++) {
            const int j = j0 + rep * 512 + tid;
            float acc[64];
#pragma unroll
            for (int o = 0; o < 64; o++) acc[o] = 0.0f;

            for (int c = 0; c < 64; c++) {
                float fc = features[((size_t)b * 64 + c) * NPTS + j];
#pragma unroll
                for (int o4 = 0; o4 < 64; o4 += 4) {
                    float4 wv = *(const float4*)&w0t[c][o4];
                    acc[o4 + 0] = fmaf(wv.x, fc, acc[o4 + 0]);
                    acc[o4 + 1] = fmaf(wv.y, fc, acc[o4 + 1]);
                    acc[o4 + 2] = fmaf(wv.z, fc, acc[o4 + 2]);
                    acc[o4 + 3] = fmaf(wv.w, fc, acc[o4 + 3]);
                }
            }
            float* op = g_F0 + ((size_t)b * NPTS + j) * 64;
#pragma unroll
            for (int o4 = 0; o4 < 64; o4 += 4)
                *(float4*)(op + o4) = make_float4(acc[o4], acc[o4+1], acc[o4+2], acc[o4+3]);
        }

        __threadfence();
        __syncthreads();
        if (tid == 0) atomicAdd(&g_f0done[b * 32], 1u);
        return;
    }

    // =================================================================
    // ROLE 3: worker — INTERLEAVED mapping: batch = g&7, group = g>>3
    // =================================================================
    {
        const int g = bid - 72;
        const int b = g & 7;
        const int s0 = (g >> 3) * 8;

        float* sW1 = sm;                       // [c][o] 64x64
        float* sW2 = sm + 4096;                // [c][o] 64x128
        float* sX0 = sm + 12288;               // [c][m] 64 x XROW
        float* sX1 = sm + 12288 + 64 * XROW;
        float4* sWXB = (float4*)(sm + 12288 + 128 * XROW);
        float* sB1 = sm + 12288 + 128 * XROW + 256;
        float* sB2 = sB1 + 64;
        __shared__ int s_bq[8][NSAMP];

        // ---- load weights while waiting is pending ----
        for (int i = tid; i < 4096; i += MLPT) {
            int c = i >> 6, o = i & 63;
            sW1[c * 64 + o] = w1[o * 64 + c];
        }
        for (int i = tid; i < 8192; i += MLPT) {
            int c = i >> 7, o = i & 127;
            sW2[c * 128 + o] = w2[o * 64 + c];
        }
        if (tid < 64) {
            sWXB[tid] = make_float4(w0[tid * C0IN + 0], w0[tid * C0IN + 1],
                                    w0[tid * C0IN + 2], b0[tid]);
            sB1[tid] = b1[tid];
        }
        if (tid < 128) sB2[tid] = b2[tid];

        // ---- wait for FPS centers + F0 of this batch ----
        if (tid == 0) {
            while (ld_acq(&g_progress[b * 32]) < (unsigned)(s0 + 8)) __nanosleep(1024);
            while (ld_acq(&g_f0done[b * 32]) < 8u) __nanosleep(1024);
        }
        __syncthreads();

        // ---- in-block ball query: warp w handles center s0+w ----
        {
            const int lane = tid & 31, w = tid >> 5;
            if (w < 8) {
                const int sg = s0 + w;
                const float* cz = new_xyz + ((size_t)b * NCTR + sg) * 3;
                const float cx = cz[0], cy = cz[1], czz = cz[2];
                const float* pb = pos + (size_t)b * NPTS * 3;

                int cnt = 0, first = -1;
                for (int j0 = 0; j0 < NPTS; j0 += 32) {
                    int j = j0 + lane;
                    float dx = pb[3 * j + 0] - cx;
                    float dy = pb[3 * j + 1] - cy;
                    float dz = pb[3 * j + 2] - czz;
                    float d = fmaf(dz, dz, fmaf(dy, dy, dx * dx));
                    bool hit = d < R2;
                    unsigned bal = __ballot_sync(0xffffffffu, hit);
                    if (bal) {
                        if (first < 0) first = j0 + __ffs((int)bal) - 1;
                        int pre = __popc(bal & ((1u << lane) - 1u));
                        if (hit && cnt + pre < NSAMP) s_bq[w][cnt + pre] = j;
                        cnt += __popc(bal);
                        if (cnt >= NSAMP) break;
                    }
                }
                if (cnt < NSAMP) {
                    int pad = (first < 0) ? 0 : first;
                    if (lane >= cnt) s_bq[w][lane] = pad;
                }
            }
        }
        __syncthreads();

        // ---- phase A: build X0 (layer0 output), 256 rows x 64 ch ----
        {
            const int r = tid >> 1;
            const int h = tid & 1;
            const int o0 = h * 32;
            const int ci = r >> 5, k = r & 31;
            const int sg = s0 + ci;
            const int j = s_bq[ci][k];

            const float* pp = pos + ((size_t)b * NPTS + j) * 3;
            const float* cz = new_xyz + ((size_t)b * NCTR + sg) * 3;
            float rx = pp[0] - cz[0];
            float ry = pp[1] - cz[1];
            float rz = pp[2] - cz[2];
            const float* fp = g_F0 + ((size_t)b * NPTS + j) * 64 + o0;

#pragma unroll
            for (int o4 = 0; o4 < 32; o4 += 4) {
                float4 f = *(const float4*)(fp + o4);
                float fv[4] = { f.x, f.y, f.z, f.w };
#pragma unroll
                for (int i = 0; i < 4; i++) {
                    float4 wb = sWXB[o0 + o4 + i];
                    float v = fv[i] + wb.x * rx + wb.y * ry + wb.z * rz + wb.w;
                    sX0[(o0 + o4 + i) * XROW + r] = fmaxf(v, 0.0f);
                }
            }
        }
        __syncthreads();

        const int tm = tid & 63, tn = tid >> 6;
        const int m0 = tm * 4;

        // ---- GEMM1: X1 = relu(X0 @ W1^T + b1), 256x64, f32x2 ----
        {
            const int n0 = tn * 8;
            unsigned long long acc2[16];
#pragma unroll
            for (int i = 0; i < 16; i++) acc2[i] = 0ULL;

#pragma unroll 8
            for (int c = 0; c < 64; c++) {
                float4 a  = *(const float4*)&sX0[c * XROW + m0];
                float4 bA = *(const float4*)&sW1[c * 64 + n0];
                float4 bB = *(const float4*)&sW1[c * 64 + n0 + 4];
                unsigned long long bp[4] = { pk2(bA.x, bA.y), pk2(bA.z, bA.w),
                                             pk2(bB.x, bB.y), pk2(bB.z, bB.w) };
                unsigned long long ap[4] = { pkb(a.x), pkb(a.y), pkb(a.z), pkb(a.w) };
#pragma unroll
                for (int i = 0; i < 4; i++)
#pragma unroll
                    for (int jp = 0; jp < 4; jp++)
                        F2FMA(acc2[i * 4 + jp], ap[i], bp[jp], acc2[i * 4 + jp]);
            }

#pragma unroll
            for (int jp = 0; jp < 4; jp++) {
                float lo[4], hi[4];
#pragma unroll
                for (int i = 0; i < 4; i++) upk2(acc2[i * 4 + jp], lo[i], hi[i]);
                float bb0 = sB1[n0 + 2 * jp], bb1 = sB1[n0 + 2 * jp + 1];
                float4 v0, v1;
                v0.x = fmaxf(lo[0] + bb0, 0.0f); v0.y = fmaxf(lo[1] + bb0, 0.0f);
                v0.z = fmaxf(lo[2] + bb0, 0.0f); v0.w = fmaxf(lo[3] + bb0, 0.0f);
                v1.x = fmaxf(hi[0] + bb1, 0.0f); v1.y = fmaxf(hi[1] + bb1, 0.0f);
                v1.z = fmaxf(hi[2] + bb1, 0.0f); v1.w = fmaxf(hi[3] + bb1, 0.0f);
                *(float4*)&sX1[(n0 + 2 * jp)     * XROW + m0] = v0;
                *(float4*)&sX1[(n0 + 2 * jp + 1) * XROW + m0] = v1;
            }
        }
        __syncthreads();

        // ---- GEMM2: 256x128, f32x2, fold max+bias+relu ----
        {
            const int n2 = tn * 16;
            unsigned long long acc2[32];
#pragma unroll
            for (int i = 0; i < 32; i++) acc2[i] = 0ULL;

#pragma unroll 4
            for (int c = 0; c < 64; c++) {
                float4 a = *(const float4*)&sX1[c * XROW + m0];
                unsigned long long ap[4] = { pkb(a.x), pkb(a.y), pkb(a.z), pkb(a.w) };
                unsigned long long bp[8];
#pragma unroll
                for (int q = 0; q < 4; q++) {
                    float4 bb = *(const float4*)&sW2[c * 128 + n2 + 4 * q];
                    bp[2 * q]     = pk2(bb.x, bb.y);
                    bp[2 * q + 1] = pk2(bb.z, bb.w);
                }
#pragma unroll
                for (int i = 0; i < 4; i++)
#pragma unroll
                    for (int jp = 0; jp < 8; jp++)
                        F2FMA(acc2[i * 8 + jp], ap[i], bp[jp], acc2[i * 8 + jp]);
            }

            const int center = tm >> 3;
#pragma unroll
            for (int jp = 0; jp < 8; jp++) {
                float lo[4], hi[4];
#pragma unroll
                for (int i = 0; i < 4; i++) upk2(acc2[i * 8 + jp], lo[i], hi[i]);
                float vlo = fmaxf(fmaxf(lo[0], lo[1]), fmaxf(lo[2], lo[3]));
                float vhi = fmaxf(fmaxf(hi[0], hi[1]), fmaxf(hi[2], hi[3]));
                vlo = fmaxf(vlo, __shfl_xor_sync(0xffffffffu, vlo, 1));
                vhi = fmaxf(vhi, __shfl_xor_sync(0xffffffffu, vhi, 1));
                vlo = fmaxf(vlo, __shfl_xor_sync(0xffffffffu, vlo, 2));
                vhi = fmaxf(vhi, __shfl_xor_sync(0xffffffffu, vhi, 2));
                vlo = fmaxf(vlo, __shfl_xor_sync(0xffffffffu, vlo, 4));
                vhi = fmaxf(vhi, __shfl_xor_sync(0xffffffffu, vhi, 4));
                if ((tm & 7) == 0) {
                    int n = n2 + 2 * jp;
                    out_feat[((size_t)b * C2 + n)     * NCTR + (s0 + center)] =
                        fmaxf(vlo + sB2[n], 0.0f);
                    out_feat[((size_t)b * C2 + n + 1) * NCTR + (s0 + center)] =
                        fmaxf(vhi + sB2[n + 1], 0.0f);
                }
            }
        }
    }
}

// =====================================================================
extern "C" void kernel_launch(void* const* d_in, const int* in_sizes, int n_in,
                              void* d_out, int out_size)
{
    const float* pos      = (const float*)d_in[0];
    const float* features = (const float*)d_in[1];
    const float* w0       = (const float*)d_in[2];
    const float* b0       = (const float*)d_in[3];
    const float* w1       = (const float*)d_in[4];
    const float* b1       = (const float*)d_in[5];
    const float* w2       = (const float*)d_in[6];
    const float* b2       = (const float*)d_in[7];

    float* out = (float*)d_out;
    float* new_xyz  = out;                               // (8, 2048, 3)
    float* out_feat = out + (size_t)BATCH * NCTR * 3;    // (8, 128, 2048)

    reset_kernel<<<1, 256>>>();

    cudaFuncSetAttribute(mega_kernel,
                         cudaFuncAttributeMaxDynamicSharedMemorySize,
                         SMEM_FLOATS * sizeof(float));
    mega_kernel<<<GRID_TOTAL, MLPT, SMEM_FLOATS * sizeof(float)>>>(
        pos, features, w0, b0, w1, b1, w2, b2, new_xyz, out_feat);
}

// round 16
// speedup vs baseline: 1.0138x; 1.0138x over previous
#include <cuda_runtime.h>
#include <cuda_bf16.h>
#include <cstdint>

#define BATCH 8
#define NPTS  8192
#define NCTR  2048          // NPTS * 0.25
#define NSAMP 32
#define C0IN  67
#define C2    128
#define R2    0.25f         // radius^2

// ---------------- scratch (device globals; no allocation allowed) ----------------
__device__ float    g_F0[(size_t)BATCH * NPTS * 64];     // 16 MB, layout (b, j, o)
__device__ unsigned g_progress[BATCH * 32];              // padded: 1 line per batch
__device__ unsigned g_f0done[BATCH * 32];                // padded: 1 line per batch

// ---------------- f32x2 packed helpers ----------------
__device__ __forceinline__ unsigned long long pk2(float lo, float hi) {
    unsigned long long r;
    asm("mov.b64 %0, {%1, %2};" : "=l"(r) : "f"(lo), "f"(hi));
    return r;
}
__device__ __forceinline__ unsigned long long pkb(float v) { return pk2(v, v); }
__device__ __forceinline__ void upk2(unsigned long long v, float& lo, float& hi) {
    asm("mov.b64 {%0, %1}, %2;" : "=f"(lo), "=f"(hi) : "l"(v));
}
#define F2FMA(d, a, b, c) asm("fma.rn.f32x2 %0, %1, %2, %3;" : "=l"(d) : "l"(a), "l"(b), "l"(c))
#define F2ADD(d, a, b)    asm("add.rn.f32x2 %0, %1, %2;"     : "=l"(d) : "l"(a), "l"(b))
#define F2MUL(d, a, b)    asm("mul.rn.f32x2 %0, %1, %2;"     : "=l"(d) : "l"(a), "l"(b))

// ---------------- acquire/release helpers ----------------
__device__ __forceinline__ unsigned ld_acq(const unsigned* p) {
    unsigned v;
    asm volatile("ld.acquire.gpu.global.u32 %0, [%1];" : "=r"(v) : "l"(p) : "memory");
    return v;
}
__device__ __forceinline__ void st_rel(unsigned* p, unsigned v) {
    asm volatile("st.release.gpu.global.u32 [%0], %1;" :: "l"(p), "r"(v) : "memory");
}

__device__ __forceinline__ int expand3(int v) {     // 3-bit -> bits 0,3,6
    return (v & 1) | ((v & 2) << 2) | ((v & 4) << 4);
}

// =====================================================================
// reset: clear the inter-block flags (needed per graph replay)
// =====================================================================
__global__ void reset_kernel()
{
    if (threadIdx.x < BATCH * 32) {
        g_progress[threadIdx.x] = 0;
        g_f0done[threadIdx.x]  = 0;
    }
}

// =====================================================================
// mega-kernel: bid 0-7 FPS | bid 8-71 F0 | bid 72+ ballq+MLP workers
// =====================================================================
#define MLPT 512
#define XROW 260
#define SMEM_FLOATS (4096 + 8192 + 64*XROW + 64*XROW + 256 + 64 + 128)
#define GRID_TOTAL (8 + 64 + BATCH * NCTR / 8)

__global__ void __launch_bounds__(MLPT, 1)
mega_kernel(const float* __restrict__ pos,
            const float* __restrict__ features,
            const float* __restrict__ w0, const float* __restrict__ b0,
            const float* __restrict__ w1, const float* __restrict__ b1,
            const float* __restrict__ w2, const float* __restrict__ b2,
            float* __restrict__ new_xyz,
            float* __restrict__ out_feat)
{
    const int bid = blockIdx.x;
    const int tid = threadIdx.x;
    extern __shared__ float sm[];

    // =================================================================
    // ROLE 1: FPS — whole-warp exact bbox prune (register-resident bbox),
    // Morton-sorted chunks, fused 64-bit key reduction, 1 barrier/step.
    // =================================================================
    if (bid < 8) {
        const int b = bid;
        const int t = tid;
        const int lane = t & 31, w = t >> 5;
        const float* pb = pos + (size_t)b * NPTS * 3;

        float4*   s_pos4 = (float4*)sm;                  // orig-indexed, NEGATED
        unsigned* s_soid = (unsigned*)(sm + 32768);      // sorted pos -> orig idx
        int*      s_hist = (int*)(sm + 40960);           // 512 bins
        int*      s_wsum = (int*)(sm + 41472);           // 16
        float*    s_gbb  = sm + 41488;                   // 6 global bbox

        __shared__ unsigned long long s_key[2][16];      // (wmax<<32)|vlo per warp
        __shared__ float s_red[6][16];

        // ---- pass 1: load points, fill negated table, local bbox ----
        float mnx = 1e30f, mny = 1e30f, mnz = 1e30f;
        float mxx = -1e30f, mxy = -1e30f, mxz = -1e30f;
        for (int k = 0; k < 16; k++) {
            int p = t + (k << 9);
            float px = pb[3 * p], py = pb[3 * p + 1], pz = pb[3 * p + 2];
            s_pos4[p] = make_float4(-px, -py, -pz, 0.0f);
            mnx = fminf(mnx, px); mxx = fmaxf(mxx, px);
            mny = fminf(mny, py); mxy = fmaxf(mxy, py);
            mnz = fminf(mnz, pz); mxz = fmaxf(mxz, pz);
        }
#pragma unroll
        for (int o = 16; o > 0; o >>= 1) {
            mnx = fminf(mnx, __shfl_xor_sync(0xffffffffu, mnx, o));
            mny = fminf(mny, __shfl_xor_sync(0xffffffffu, mny, o));
            mnz = fminf(mnz, __shfl_xor_sync(0xffffffffu, mnz, o));
            mxx = fmaxf(mxx, __shfl_xor_sync(0xffffffffu, mxx, o));
            mxy = fmaxf(mxy, __shfl_xor_sync(0xffffffffu, mxy, o));
            mxz = fmaxf(mxz, __shfl_xor_sync(0xffffffffu, mxz, o));
        }
        if (lane == 0) {
            s_red[0][w] = mnx; s_red[1][w] = mny; s_red[2][w] = mnz;
            s_red[3][w] = mxx; s_red[4][w] = mxy; s_red[5][w] = mxz;
        }
        s_hist[t] = 0;
        __syncthreads();
        if (w == 0 && lane < 6) {
            float v = s_red[lane][0];
            for (int i = 1; i < 16; i++)
                v = (lane < 3) ? fminf(v, s_red[lane][i]) : fmaxf(v, s_red[lane][i]);
            s_gbb[lane] = v;
        }
        __syncthreads();

        // ---- pass 2: morton keys + histogram ----
        const float bnx = s_gbb[0], bny = s_gbb[1], bnz = s_gbb[2];
        const float sx = 7.9999f / fmaxf(s_gbb[3] - bnx, 1e-20f);
        const float sy = 7.9999f / fmaxf(s_gbb[4] - bny, 1e-20f);
        const float sz = 7.9999f / fmaxf(s_gbb[5] - bnz, 1e-20f);
        unsigned key[16];
        for (int k = 0; k < 16; k++) {
            float4 f = s_pos4[t + (k << 9)];
            int qx = min(7, (int)((-f.x - bnx) * sx));
            int qy = min(7, (int)((-f.y - bny) * sy));
            int qz = min(7, (int)((-f.z - bnz) * sz));
            key[k] = (unsigned)(expand3(qx) | (expand3(qy) << 1) | (expand3(qz) << 2));
            atomicAdd(&s_hist[key[k]], 1);
        }
        __syncthreads();

        // ---- exclusive scan of 512 bins ----
        {
            int v = s_hist[t];
            int inc = v;
#pragma unroll
            for (int o = 1; o < 32; o <<= 1) {
                int n = __shfl_up_sync(0xffffffffu, inc, o);
                if (lane >= o) inc += n;
            }
            if (lane == 31) s_wsum[w] = inc;
            __syncthreads();
            if (w == 0) {
                int ws = (lane < 16) ? s_wsum[lane] : 0;
                int wi = ws;
#pragma unroll
                for (int o = 1; o < 16; o <<= 1) {
                    int n = __shfl_up_sync(0xffffffffu, wi, o);
                    if (lane >= o) wi += n;
                }
                if (lane < 16) s_wsum[lane] = wi - ws;
            }
            __syncthreads();
            int excl = inc - v + s_wsum[w];
            __syncthreads();
            s_hist[t] = excl;
            __syncthreads();
        }

        // ---- scatter: sorted position -> orig idx ----
        for (int k = 0; k < 16; k++) {
            int d = atomicAdd(&s_hist[key[k]], 1);
            s_soid[d] = (unsigned)(t + (k << 9));
        }
        __syncthreads();

        // ---- pack registers from sorted order + REGISTER warp bbox ----
        unsigned long long xp[8], yp[8], zp[8];
        float dm[16];
        float bxn = 1e30f, byn = 1e30f, bzn = 1e30f;
        float bxx = -1e30f, byx = -1e30f, bzx = -1e30f;
#pragma unroll
        for (int k = 0; k < 8; k++) {
            int p0 = (w << 9) + (k << 6) + lane;
            int p1 = p0 + 32;
            float4 a  = s_pos4[s_soid[p0]];
            float4 c4 = s_pos4[s_soid[p1]];
            float ax = -a.x, ay = -a.y, az = -a.z;       // positive coords
            float cx = -c4.x, cy = -c4.y, cz2 = -c4.z;
            xp[k] = pk2(ax, cx); yp[k] = pk2(ay, cy); zp[k] = pk2(az, cz2);
            dm[2 * k] = 1e10f; dm[2 * k + 1] = 1e10f;
            bxn = fminf(bxn, fminf(ax, cx)); bxx = fmaxf(bxx, fmaxf(ax, cx));
            byn = fminf(byn, fminf(ay, cy)); byx = fmaxf(byx, fmaxf(ay, cy));
            bzn = fminf(bzn, fminf(az, cz2)); bzx = fmaxf(bzx, fmaxf(az, cz2));
        }
#pragma unroll
        for (int o = 16; o > 0; o >>= 1) {
            bxn = fminf(bxn, __shfl_xor_sync(0xffffffffu, bxn, o));
            byn = fminf(byn, __shfl_xor_sync(0xffffffffu, byn, o));
            bzn = fminf(bzn, __shfl_xor_sync(0xffffffffu, bzn, o));
            bxx = fmaxf(bxx, __shfl_xor_sync(0xffffffffu, bxx, o));
            byx = fmaxf(byx, __shfl_xor_sync(0xffffffffu, byx, o));
            bzx = fmaxf(bzx, __shfl_xor_sync(0xffffffffu, bzx, o));
        }
        if (t == 0) {
            float* nz = new_xyz + (size_t)b * NCTR * 3;
            nz[0] = pb[0]; nz[1] = pb[1]; nz[2] = pb[2];
        }
        __syncthreads();

        float4 nc = s_pos4[0];                        // negated current center
        unsigned wmax_cur = __float_as_uint(1e10f);   // warp dm max (bits)
        unsigned vlo_cur = 0;                         // 8192 - argmin-idx

        for (int s = 1; s < NCTR; ++s) {
            const int buf = s & 1;

            // ---- whole-warp exact bbox prune (bbox in REGISTERS;
            //      nc is NEGATED center -> bxn + nc.x = min_x - cx) ----
            float ddx = fmaxf(fmaxf(bxn + nc.x, -(bxx + nc.x)), 0.0f);
            float ddy = fmaxf(fmaxf(byn + nc.y, -(byx + nc.y)), 0.0f);
            float ddz = fmaxf(fmaxf(bzn + nc.z, -(bzx + nc.z)), 0.0f);
            float dbb = ddx * ddx;
            dbb = fmaf(ddy, ddy, dbb);
            dbb = fmaf(ddz, ddz, dbb);
            // EXACT: dbb > wmax*1.0001 (margin >> fp error) implies every
            // point's new distance exceeds its dm -> min() is identity.
            if (!(dbb > __uint_as_float(wmax_cur) * 1.0001f)) {
                const unsigned long long nx  = pkb(nc.x);
                const unsigned long long ny  = pkb(nc.y);
                const unsigned long long nzp = pkb(nc.z);
#pragma unroll
                for (int k = 0; k < 8; k++) {
                    unsigned long long dx, dy, dz, sq;
                    F2ADD(dx, xp[k], nx);
                    F2ADD(dy, yp[k], ny);
                    F2ADD(dz, zp[k], nzp);
                    F2MUL(sq, dx, dx);
                    F2FMA(sq, dy, dy, sq);
                    F2FMA(sq, dz, dz, sq);       // == scalar fmaf chain (exact)
                    float lo, hi; upk2(sq, lo, hi);
                    dm[2 * k]     = fminf(dm[2 * k], lo);
                    dm[2 * k + 1] = fminf(dm[2 * k + 1], hi);
                }

                // ---- pairwise max tree over 16 dm (depth 4) ----
                float t8[8];
#pragma unroll
                for (int i = 0; i < 8; i++) t8[i] = fmaxf(dm[2 * i], dm[2 * i + 1]);
                float q0 = fmaxf(t8[0], t8[1]), q1 = fmaxf(t8[2], t8[3]);
                float q2 = fmaxf(t8[4], t8[5]), q3 = fmaxf(t8[6], t8[7]);
                float m = fmaxf(fmaxf(q0, q1), fmaxf(q2, q3));

                unsigned mb = __float_as_uint(m);
                unsigned wmax = __reduce_max_sync(0xffffffffu, mb);
                unsigned cand = 0xffffffffu;
                if (mb == wmax) {
                    unsigned mask = 0;
#pragma unroll
                    for (int j = 0; j < 16; j++)
                        if (__float_as_uint(dm[j]) == wmax) mask |= (1u << j);
                    int j0 = __ffs(mask) - 1;
                    cand = s_soid[(w << 9) + ((j0 >> 1) << 6) + ((j0 & 1) << 5) + lane];
                    unsigned mrest = mask & (mask - 1);
                    while (mrest) {                   // rare in-thread exact ties
                        int j2 = __ffs(mrest) - 1; mrest &= mrest - 1;
                        unsigned o2 = s_soid[(w << 9) + ((j2 >> 1) << 6) + ((j2 & 1) << 5) + lane];
                        cand = min(cand, o2);
                    }
                }
                unsigned widx = __reduce_min_sync(0xffffffffu, cand);  // min ORIG idx
                wmax_cur = wmax;
                vlo_cur = 8192u - widx;
            }

            if (lane == 0)
                s_key[buf][w] = ((unsigned long long)wmax_cur << 32) | vlo_cur;
            __syncthreads();                          // the ONLY barrier per step

            // ---- fused-key reduction: one LDS.64, two REDUX ----
            unsigned long long kk = (lane < 16) ? s_key[buf][lane] : 0ULL;
            unsigned hi  = (unsigned)(kk >> 32);
            unsigned ghi = __reduce_max_sync(0xffffffffu, hi);
            unsigned lo2 = (hi == ghi) ? (unsigned)kk : 0u;
            unsigned glo = __reduce_max_sync(0xffffffffu, lo2);
            unsigned gidx = 8192u - glo;              // winner ORIG index

            nc = s_pos4[gidx];                        // one broadcast LDS.128
            if (t == 0) {
                float* nz = new_xyz + ((size_t)b * NCTR + s) * 3;
                nz[0] = -nc.x; nz[1] = -nc.y; nz[2] = -nc.z;
                if ((s & 7) == 7) st_rel(&g_progress[b * 32], (unsigned)(s + 1));
            }
        }
        return;
    }

    // =================================================================
    // ROLE 2: F0 precompute. 64 blocks: batch = fb>>3, 1024-pt chunk.
    // =================================================================
    if (bid < 72) {
        const int fb = bid - 8;
        const int b = fb >> 3;
        const int j0 = (fb & 7) * 1024;
        float (*w0t)[64] = (float(*)[64])sm;     // [c][o]

        for (int i = tid; i < 64 * 64; i += MLPT) {
            int c = i >> 6, o = i & 63;
            w0t[c][o] = w0[o * C0IN + 3 + c];
        }
        __syncthreads();

#pragma unroll
        for (int rep = 0; rep < 2; rep++) {
            const int j = j0 + rep * 512 + tid;
            float acc[64];
#pragma unroll
            for (int o = 0; o < 64; o++) acc[o] = 0.0f;

            for (int c = 0; c < 64; c++) {
                float fc = features[((size_t)b * 64 + c) * NPTS + j];
#pragma unroll
                for (int o4 = 0; o4 < 64; o4 += 4) {
                    float4 wv = *(const float4*)&w0t[c][o4];
                    acc[o4 + 0] = fmaf(wv.x, fc, acc[o4 + 0]);
                    acc[o4 + 1] = fmaf(wv.y, fc, acc[o4 + 1]);
                    acc[o4 + 2] = fmaf(wv.z, fc, acc[o4 + 2]);
                    acc[o4 + 3] = fmaf(wv.w, fc, acc[o4 + 3]);
                }
            }
            float* op = g_F0 + ((size_t)b * NPTS + j) * 64;
#pragma unroll
            for (int o4 = 0; o4 < 64; o4 += 4)
                *(float4*)(op + o4) = make_float4(acc[o4], acc[o4+1], acc[o4+2], acc[o4+3]);
        }

        __threadfence();
        __syncthreads();
        if (tid == 0) atomicAdd(&g_f0done[b * 32], 1u);
        return;
    }

    // =================================================================
    // ROLE 3: worker — INTERLEAVED mapping: batch = g&7, group = g>>3
    // =================================================================
    {
        const int g = bid - 72;
        const int b = g & 7;
        const int s0 = (g >> 3) * 8;

        float* sW1 = sm;                       // [c][o] 64x64
        float* sW2 = sm + 4096;                // [c][o] 64x128
        float* sX0 = sm + 12288;               // [c][m] 64 x XROW
        float* sX1 = sm + 12288 + 64 * XROW;
        float4* sWXB = (float4*)(sm + 12288 + 128 * XROW);
        float* sB1 = sm + 12288 + 128 * XROW + 256;
        float* sB2 = sB1 + 64;
        __shared__ int s_bq[8][NSAMP];

        // ---- load weights while waiting is pending ----
        for (int i = tid; i < 4096; i += MLPT) {
            int c = i >> 6, o = i & 63;
            sW1[c * 64 + o] = w1[o * 64 + c];
        }
        for (int i = tid; i < 8192; i += MLPT) {
            int c = i >> 7, o = i & 127;
            sW2[c * 128 + o] = w2[o * 64 + c];
        }
        if (tid < 64) {
            sWXB[tid] = make_float4(w0[tid * C0IN + 0], w0[tid * C0IN + 1],
                                    w0[tid * C0IN + 2], b0[tid]);
            sB1[tid] = b1[tid];
        }
        if (tid < 128) sB2[tid] = b2[tid];

        // ---- wait for FPS centers + F0 of this batch ----
        if (tid == 0) {
            while (ld_acq(&g_progress[b * 32]) < (unsigned)(s0 + 8)) __nanosleep(1024);
            while (ld_acq(&g_f0done[b * 32]) < 8u) __nanosleep(1024);
        }
        __syncthreads();

        // ---- in-block ball query: warp w handles center s0+w ----
        {
            const int lane = tid & 31, w = tid >> 5;
            if (w < 8) {
                const int sg = s0 + w;
                const float* cz = new_xyz + ((size_t)b * NCTR + sg) * 3;
                const float cx = cz[0], cy = cz[1], czz = cz[2];
                const float* pb = pos + (size_t)b * NPTS * 3;

                int cnt = 0, first = -1;
                for (int j0 = 0; j0 < NPTS; j0 += 32) {
                    int j = j0 + lane;
                    float dx = pb[3 * j + 0] - cx;
                    float dy = pb[3 * j + 1] - cy;
                    float dz = pb[3 * j + 2] - czz;
                    float d = fmaf(dz, dz, fmaf(dy, dy, dx * dx));
                    bool hit = d < R2;
                    unsigned bal = __ballot_sync(0xffffffffu, hit);
                    if (bal) {
                        if (first < 0) first = j0 + __ffs((int)bal) - 1;
                        int pre = __popc(bal & ((1u << lane) - 1u));
                        if (hit && cnt + pre < NSAMP) s_bq[w][cnt + pre] = j;
                        cnt += __popc(bal);
                        if (cnt >= NSAMP) break;
                    }
                }
                if (cnt < NSAMP) {
                    int pad = (first < 0) ? 0 : first;
                    if (lane >= cnt) s_bq[w][lane] = pad;
                }
            }
        }
        __syncthreads();

        // ---- phase A: build X0 (layer0 output), 256 rows x 64 ch ----
        {
            const int r = tid >> 1;
            const int h = tid & 1;
            const int o0 = h * 32;
            const int ci = r >> 5, k = r & 31;
            const int sg = s0 + ci;
            const int j = s_bq[ci][k];

            const float* pp = pos + ((size_t)b * NPTS + j) * 3;
            const float* cz = new_xyz + ((size_t)b * NCTR + sg) * 3;
            float rx = pp[0] - cz[0];
            float ry = pp[1] - cz[1];
            float rz = pp[2] - cz[2];
            const float* fp = g_F0 + ((size_t)b * NPTS + j) * 64 + o0;

#pragma unroll
            for (int o4 = 0; o4 < 32; o4 += 4) {
                float4 f = *(const float4*)(fp + o4);
                float fv[4] = { f.x, f.y, f.z, f.w };
#pragma unroll
                for (int i = 0; i < 4; i++) {
                    float4 wb = sWXB[o0 + o4 + i];
                    float v = fv[i] + wb.x * rx + wb.y * ry + wb.z * rz + wb.w;
                    sX0[(o0 + o4 + i) * XROW + r] = fmaxf(v, 0.0f);
                }
            }
        }
        __syncthreads();

        const int tm = tid & 63, tn = tid >> 6;
        const int m0 = tm * 4;

        // ---- GEMM1: X1 = relu(X0 @ W1^T + b1), 256x64, f32x2 ----
        {
            const int n0 = tn * 8;
            unsigned long long acc2[16];
#pragma unroll
            for (int i = 0; i < 16; i++) acc2[i] = 0ULL;

#pragma unroll 8
            for (int c = 0; c < 64; c++) {
                float4 a  = *(const float4*)&sX0[c * XROW + m0];
                float4 bA = *(const float4*)&sW1[c * 64 + n0];
                float4 bB = *(const float4*)&sW1[c * 64 + n0 + 4];
                unsigned long long bp[4] = { pk2(bA.x, bA.y), pk2(bA.z, bA.w),
                                             pk2(bB.x, bB.y), pk2(bB.z, bB.w) };
                unsigned long long ap[4] = { pkb(a.x), pkb(a.y), pkb(a.z), pkb(a.w) };
#pragma unroll
                for (int i = 0; i < 4; i++)
#pragma unroll
                    for (int jp = 0; jp < 4; jp++)
                        F2FMA(acc2[i * 4 + jp], ap[i], bp[jp], acc2[i * 4 + jp]);
            }

#pragma unroll
            for (int jp = 0; jp < 4; jp++) {
                float lo[4], hi[4];
#pragma unroll
                for (int i = 0; i < 4; i++) upk2(acc2[i * 4 + jp], lo[i], hi[i]);
                float bb0 = sB1[n0 + 2 * jp], bb1 = sB1[n0 + 2 * jp + 1];
                float4 v0, v1;
                v0.x = fmaxf(lo[0] + bb0, 0.0f); v0.y = fmaxf(lo[1] + bb0, 0.0f);
                v0.z = fmaxf(lo[2] + bb0, 0.0f); v0.w = fmaxf(lo[3] + bb0, 0.0f);
                v1.x = fmaxf(hi[0] + bb1, 0.0f); v1.y = fmaxf(hi[1] + bb1, 0.0f);
                v1.z = fmaxf(hi[2] + bb1, 0.0f); v1.w = fmaxf(hi[3] + bb1, 0.0f);
                *(float4*)&sX1[(n0 + 2 * jp)     * XROW + m0] = v0;
                *(float4*)&sX1[(n0 + 2 * jp + 1) * XROW + m0] = v1;
            }
        }
        __syncthreads();

        // ---- GEMM2: 256x128, f32x2, fold max+bias+relu ----
        {
            const int n2 = tn * 16;
            unsigned long long acc2[32];
#pragma unroll
            for (int i = 0; i < 32; i++) acc2[i] = 0ULL;

#pragma unroll 4
            for (int c = 0; c < 64; c++) {
                float4 a = *(const float4*)&sX1[c * XROW + m0];
                unsigned long long ap[4] = { pkb(a.x), pkb(a.y), pkb(a.z), pkb(a.w) };
                unsigned long long bp[8];
#pragma unroll
                for (int q = 0; q < 4; q++) {
                    float4 bb = *(const float4*)&sW2[c * 128 + n2 + 4 * q];
                    bp[2 * q]     = pk2(bb.x, bb.y);
                    bp[2 * q + 1] = pk2(bb.z, bb.w);
                }
#pragma unroll
                for (int i = 0; i < 4; i++)
#pragma unroll
                    for (int jp = 0; jp < 8; jp++)
                        F2FMA(acc2[i * 8 + jp], ap[i], bp[jp], acc2[i * 8 + jp]);
            }

            const int center = tm >> 3;
#pragma unroll
            for (int jp = 0; jp < 8; jp++) {
                float lo[4], hi[4];
#pragma unroll
                for (int i = 0; i < 4; i++) upk2(acc2[i * 8 + jp], lo[i], hi[i]);
                float vlo = fmaxf(fmaxf(lo[0], lo[1]), fmaxf(lo[2], lo[3]));
                float vhi = fmaxf(fmaxf(hi[0], hi[1]), fmaxf(hi[2], hi[3]));
                vlo = fmaxf(vlo, __shfl_xor_sync(0xffffffffu, vlo, 1));
                vhi = fmaxf(vhi, __shfl_xor_sync(0xffffffffu, vhi, 1));
                vlo = fmaxf(vlo, __shfl_xor_sync(0xffffffffu, vlo, 2));
                vhi = fmaxf(vhi, __shfl_xor_sync(0xffffffffu, vhi, 2));
                vlo = fmaxf(vlo, __shfl_xor_sync(0xffffffffu, vlo, 4));
                vhi = fmaxf(vhi, __shfl_xor_sync(0xffffffffu, vhi, 4));
                if ((tm & 7) == 0) {
                    int n = n2 + 2 * jp;
                    out_feat[((size_t)b * C2 + n)     * NCTR + (s0 + center)] =
                        fmaxf(vlo + sB2[n], 0.0f);
                    out_feat[((size_t)b * C2 + n + 1) * NCTR + (s0 + center)] =
                        fmaxf(vhi + sB2[n + 1], 0.0f);
                }
            }
        }
    }
}

// =====================================================================
extern "C" void kernel_launch(void* const* d_in, const int* in_sizes, int n_in,
                              void* d_out, int out_size)
{
    const float* pos      = (const float*)d_in[0];
    const float* features = (const float*)d_in[1];
    const float* w0       = (const float*)d_in[2];
    const float* b0       = (const float*)d_in[3];
    const float* w1       = (const float*)d_in[4];
    const float* b1       = (const float*)d_in[5];
    const float* w2       = (const float*)d_in[6];
    const float* b2       = (const float*)d_in[7];

    float* out = (float*)d_out;
    float* new_xyz  = out;                               // (8, 2048, 3)
    float* out_feat = out + (size_t)BATCH * NCTR * 3;    // (8, 128, 2048)

    reset_kernel<<<1, 256>>>();

    cudaFuncSetAttribute(mega_kernel,
                         cudaFuncAttributeMaxDynamicSharedMemorySize,
                         SMEM_FLOATS * sizeof(float));
    mega_kernel<<<GRID_TOTAL, MLPT, SMEM_FLOATS * sizeof(float)>>>(
        pos, features, w0, b0, w1, b1, w2, b2, new_xyz, out_feat);
}